// round 8
// baseline (speedup 1.0000x reference)
#include <cuda_runtime.h>
#include <mma.h>
#include <cstdint>

using namespace nvcuda;

#define MTOK  8192
#define D_    768
#define NCODE 16384
#define THRv  100.0f

#define BM 128
#define BN 128
#define BK 32
#define NSPLIT 16
#define NCHUNK (NCODE / NSPLIT)       // 1024
#define NTILES (NCHUNK / BN)          // 8
#define NKSTEP (D_ / BK)              // 24
#define SROWF  36                     // padded fp32 smem row (floats); 144B pitch (16B-aligned)
#define NCAND  (NSPLIT * NTILES)      // 128 candidates per token

// Scratch (static device memory — allocations are forbidden)
__device__ float g_c2[NCODE];
__device__ float g_x2[MTOK];
__device__ unsigned long long g_cand[MTOK * NCAND];

// ---------------------------------------------------------------------------
// c2[n] = sum codes[n]^2 (exact fp32), +inf if inactive (uint8 or int32 bool).
__global__ void prep_c2_kernel(const float* __restrict__ codes,
                               const unsigned char* __restrict__ act8) {
    int n = blockIdx.x;
    const float* row = codes + (size_t)n * D_;
    float s = 0.f;
    for (int d = threadIdx.x; d < D_; d += 128) { float v = row[d]; s += v * v; }
    __shared__ float red[128];
    red[threadIdx.x] = s;
    __syncthreads();
    for (int off = 64; off; off >>= 1) {
        if (threadIdx.x < off) red[threadIdx.x] += red[threadIdx.x + off];
        __syncthreads();
    }
    if (threadIdx.x == 0) {
        bool int32mode = (act8[0] == 1) && (act8[1] == 0) && (act8[2] == 0) && (act8[3] == 0);
        bool a = int32mode ? (((const int*)act8)[n] != 0) : (act8[n] != 0);
        g_c2[n] = a ? red[0] : __int_as_float(0x7f800000);
    }
}

__global__ void prep_x2_kernel(const float* __restrict__ x) {
    int t = blockIdx.x;
    const float* row = x + (size_t)t * D_;
    float s = 0.f;
    for (int d = threadIdx.x; d < D_; d += 128) { float v = row[d]; s += v * v; }
    __shared__ float red[128];
    red[threadIdx.x] = s;
    __syncthreads();
    for (int off = 64; off; off >>= 1) {
        if (threadIdx.x < off) red[threadIdx.x] += red[threadIdx.x + off];
        __syncthreads();
    }
    if (threadIdx.x == 0) g_x2[t] = red[0];
}

__global__ void init_cand_kernel() {
    int i = blockIdx.x * blockDim.x + threadIdx.x;
    if (i < MTOK * NCAND) g_cand[i] = 0xFFFFFFFFFFFFFFFFULL;
}

// ---------------------------------------------------------------------------
__device__ __forceinline__ unsigned float_to_ordered(float f) {
    unsigned b = __float_as_uint(f);
    return (b & 0x80000000u) ? ~b : (b | 0x80000000u);
}

#define CP16(dst, src) \
    asm volatile("cp.async.cg.shared.global [%0], [%1], 16;\n" ::"r"(dst), "l"(src))
#define CP_COMMIT() asm volatile("cp.async.commit_group;\n" ::)
#define CP_WAIT0()  asm volatile("cp.async.wait_group 0;\n" ::)

// ---------------------------------------------------------------------------
// Selection GEMM: tf32 WMMA (16x16x8) direct from fp32 inputs, 2-stage
// cp.async double buffering. Per-token per-TILE winner nominated for rescore.
// ---------------------------------------------------------------------------
__global__ __launch_bounds__(256) void gemm_tf32_kernel(const float* __restrict__ x,
                                                        const float* __restrict__ codes) {
    __shared__ __align__(16) float sA[2][BM * SROWF];
    __shared__ __align__(16) float sB[2][BN * SROWF];
    __shared__ __align__(16) float sbuf[8][16 * 16];

    const int tid  = threadIdx.x;
    const int lane = tid & 31;
    const int warp = tid >> 5;
    const int wm = warp >> 1;    // 0..3 -> 32 rows each
    const int wn = warp & 1;     // 0..1 -> 64 cols each
    const int mBase  = blockIdx.x * BM;
    const int nChunk = blockIdx.y * NCHUNK;

    const uint32_t sAb = (uint32_t)__cvta_generic_to_shared(&sA[0][0]);
    const uint32_t sBb = (uint32_t)__cvta_generic_to_shared(&sB[0][0]);
    const int STAGEB = BM * SROWF * 4;   // bytes per stage

    const int lr0  = tid >> 2;           // rows 0..63 (and +64)
    const int lseg = (tid & 3) * 8;      // float offset 0,8,16,24 (32B)

    const float* Asrc0 = x + (size_t)(mBase + lr0) * D_ + lseg;
    const float* Asrc1 = x + (size_t)(mBase + lr0 + 64) * D_ + lseg;

    // smem byte offsets for this thread's 8 cp.async destinations (per stage)
    const uint32_t oA0 = (lr0 * SROWF + lseg) * 4;
    const uint32_t oA1 = ((lr0 + 64) * SROWF + lseg) * 4;

    for (int nt = 0; nt < NTILES; nt++) {
        const int nBase = nChunk + nt * BN;
        const float* Bsrc0 = codes + (size_t)(nBase + lr0) * D_ + lseg;
        const float* Bsrc1 = codes + (size_t)(nBase + lr0 + 64) * D_ + lseg;

        wmma::fragment<wmma::accumulator, 16, 16, 8, float> acc[2][4];
#pragma unroll
        for (int mi = 0; mi < 2; mi++)
#pragma unroll
            for (int ni = 0; ni < 4; ni++) wmma::fill_fragment(acc[mi][ni], 0.0f);

        // prefetch k-step 0 into stage 0 (barrier inside prev iteration's loop
        // already ordered all compute on stage 0 before this point)
        {
            CP16(sAb + oA0,      Asrc0); CP16(sAb + oA0 + 16, Asrc0 + 4);
            CP16(sAb + oA1,      Asrc1); CP16(sAb + oA1 + 16, Asrc1 + 4);
            CP16(sBb + oA0,      Bsrc0); CP16(sBb + oA0 + 16, Bsrc0 + 4);
            CP16(sBb + oA1,      Bsrc1); CP16(sBb + oA1 + 16, Bsrc1 + 4);
            CP_COMMIT();
        }

        for (int kb = 0; kb < NKSTEP; kb++) {
            CP_WAIT0();
            __syncthreads();
            if (kb + 1 < NKSTEP) {
                const int st = (kb + 1) & 1;
                const int kg = (kb + 1) * BK;
                CP16(sAb + st * STAGEB + oA0,      Asrc0 + kg);
                CP16(sAb + st * STAGEB + oA0 + 16, Asrc0 + kg + 4);
                CP16(sAb + st * STAGEB + oA1,      Asrc1 + kg);
                CP16(sAb + st * STAGEB + oA1 + 16, Asrc1 + kg + 4);
                CP16(sBb + st * STAGEB + oA0,      Bsrc0 + kg);
                CP16(sBb + st * STAGEB + oA0 + 16, Bsrc0 + kg + 4);
                CP16(sBb + st * STAGEB + oA1,      Bsrc1 + kg);
                CP16(sBb + st * STAGEB + oA1 + 16, Bsrc1 + kg + 4);
                CP_COMMIT();
            }
            const int st = kb & 1;
#pragma unroll
            for (int ks = 0; ks < 4; ks++) {
                wmma::fragment<wmma::matrix_a, 16, 16, 8, wmma::precision::tf32, wmma::row_major> fa[2];
#pragma unroll
                for (int mi = 0; mi < 2; mi++) {
                    wmma::load_matrix_sync(fa[mi], &sA[st][(wm * 32 + mi * 16) * SROWF + ks * 8], SROWF);
#pragma unroll
                    for (int e = 0; e < fa[mi].num_elements; e++)
                        fa[mi].x[e] = wmma::__float_to_tf32(fa[mi].x[e]);
                }
#pragma unroll
                for (int ni = 0; ni < 4; ni++) {
                    // smem B is [n][k]; as a KxN matrix that's col_major with ldm=SROWF
                    wmma::fragment<wmma::matrix_b, 16, 16, 8, wmma::precision::tf32, wmma::col_major> fb;
                    wmma::load_matrix_sync(fb, &sB[st][(wn * 64 + ni * 16) * SROWF + ks * 8], SROWF);
#pragma unroll
                    for (int e = 0; e < fb.num_elements; e++)
                        fb.x[e] = wmma::__float_to_tf32(fb.x[e]);
                    wmma::mma_sync(acc[0][ni], fa[0], fb, acc[0][ni]);
                    wmma::mma_sync(acc[1][ni], fa[1], fb, acc[1][ni]);
                }
            }
        }

        // epilogue: drain frags (explicit indices), per-TILE min per row, nominate.
        float bestv[2];
        int   besti[2];
#pragma unroll
        for (int q = 0; q < 2; q++) { bestv[q] = __int_as_float(0x7f800000); besti[q] = nBase; }

#pragma unroll
        for (int mi = 0; mi < 2; mi++) {
#pragma unroll
            for (int ni = 0; ni < 4; ni++) {
                wmma::store_matrix_sync(&sbuf[warp][0], acc[mi][ni], 16, wmma::mem_row_major);
                __syncwarp();
                const int lr = lane >> 1;
                const int cb = (lane & 1) * 8;
                const int gcol0 = nBase + wn * 64 + ni * 16 + cb;
#pragma unroll
                for (int c = 0; c < 8; c++) {
                    float dot = sbuf[warp][lr * 16 + cb + c];
                    float s = fmaf(-2.0f, dot, g_c2[gcol0 + c]);
                    if (s < bestv[mi]) { bestv[mi] = s; besti[mi] = gcol0 + c; }
                }
                __syncwarp();
            }
        }

        const int slot = blockIdx.y * NTILES + nt;
#pragma unroll
        for (int mi = 0; mi < 2; mi++) {
            unsigned long long key =
                (((unsigned long long)float_to_ordered(bestv[mi])) << 32) | (unsigned)besti[mi];
            unsigned long long o = __shfl_xor_sync(0xffffffffu, key, 1);
            if (o < key) key = o;
            if ((lane & 1) == 0) {
                int row = mBase + wm * 32 + mi * 16 + (lane >> 1);
                atomicMin(&g_cand[(size_t)row * NCAND + slot], key);
            }
        }
    }
}

// ---------------------------------------------------------------------------
// Exact fp32 rescoring of the 128 nominees per token; emits final outputs.
// ---------------------------------------------------------------------------
__global__ __launch_bounds__(256) void refine_kernel(const float* __restrict__ x,
                                                     const float* __restrict__ codes,
                                                     float* __restrict__ out, int out_size) {
    const int t = blockIdx.x * 8 + (threadIdx.x >> 5);
    const int lane = threadIdx.x & 31;
    if (t >= MTOK) return;

    const float4* xr = (const float4*)(x + (size_t)t * D_);
    float4 xv[6];
#pragma unroll
    for (int j = 0; j < 6; j++) xv[j] = xr[lane + j * 32];

    unsigned long long best = 0xFFFFFFFFFFFFFFFFULL;

    for (int c = 0; c < NCAND; c++) {
        unsigned idx = (unsigned)(g_cand[(size_t)t * NCAND + c] & 0xffffffffu);
        if (idx >= NCODE) continue;             // unwritten/poisoned slot guard
        const float4* cr = (const float4*)(codes + (size_t)idx * D_);
        float s = 0.f;
#pragma unroll
        for (int j = 0; j < 6; j++) {
            float4 cv = cr[lane + j * 32];
            s += xv[j].x * cv.x + xv[j].y * cv.y + xv[j].z * cv.z + xv[j].w * cv.w;
        }
#pragma unroll
        for (int off = 16; off; off >>= 1) s += __shfl_xor_sync(0xffffffffu, s, off);
        float dist = fmaf(-2.0f, s, g_c2[idx]);   // exact fp32 score; inf if inactive
        unsigned long long key =
            (((unsigned long long)float_to_ordered(dist)) << 32) | (unsigned long long)idx;
        if (key < best) best = key;
    }

    if (lane == 0) {
        unsigned u = (unsigned)(best >> 32);
        unsigned b = (u & 0x80000000u) ? (u & 0x7fffffffu) : ~u;
        float s = __uint_as_float(b);
        int idx = (int)(best & 0xffffffffu);
        float dmin = g_x2[t] + s;
        int idx_out = (dmin <= THRv) ? idx : -1;
        if (best == 0xFFFFFFFFFFFFFFFFULL) { idx_out = -1; dmin = __int_as_float(0x7f800000); }
        out[t] = (float)idx_out;
        if (out_size >= 2 * MTOK) out[MTOK + t] = dmin;
    }
}

// ---------------------------------------------------------------------------
extern "C" void kernel_launch(void* const* d_in, const int* in_sizes, int n_in,
                              void* d_out, int out_size) {
    const float* x     = (const float*)d_in[0];
    const float* codes = (const float*)d_in[1];
    const unsigned char* act = (const unsigned char*)d_in[2];

    prep_c2_kernel<<<NCODE, 128>>>(codes, act);
    prep_x2_kernel<<<MTOK, 128>>>(x);
    init_cand_kernel<<<(MTOK * NCAND + 255) / 256, 256>>>();
    gemm_tf32_kernel<<<dim3(MTOK / BM, NSPLIT), 256>>>(x, codes);
    refine_kernel<<<MTOK / 8, 256>>>(x, codes, (float*)d_out, out_size);
}

// round 9
// speedup vs baseline: 1.1749x; 1.1749x over previous
#include <cuda_runtime.h>
#include <mma.h>
#include <cstdint>

using namespace nvcuda;

#define MTOK  8192
#define D_    768
#define NCODE 16384
#define THRv  100.0f

#define BM 128
#define BN 128
#define BK 32
#define NSPLIT 16
#define NCHUNK (NCODE / NSPLIT)       // 1024
#define NTILES (NCHUNK / BN)          // 8
#define NKSTEP (D_ / BK)              // 24
#define SROWF  36                     // padded fp32 smem row (floats); 144B pitch
#define NCAND  (NSPLIT * NTILES)      // 128 candidates per token

// Scratch (static device memory — allocations are forbidden)
__device__ float g_c2[NCODE];
__device__ float g_x2[MTOK];
__device__ unsigned long long g_cand[MTOK * NCAND];

// ---------------------------------------------------------------------------
// c2[n] = sum codes[n]^2 (exact fp32), +inf if inactive (uint8 or int32 bool).
__global__ void prep_c2_kernel(const float* __restrict__ codes,
                               const unsigned char* __restrict__ act8) {
    int n = blockIdx.x;
    const float* row = codes + (size_t)n * D_;
    float s = 0.f;
    for (int d = threadIdx.x; d < D_; d += 128) { float v = row[d]; s += v * v; }
    __shared__ float red[128];
    red[threadIdx.x] = s;
    __syncthreads();
    for (int off = 64; off; off >>= 1) {
        if (threadIdx.x < off) red[threadIdx.x] += red[threadIdx.x + off];
        __syncthreads();
    }
    if (threadIdx.x == 0) {
        bool int32mode = (act8[0] == 1) && (act8[1] == 0) && (act8[2] == 0) && (act8[3] == 0);
        bool a = int32mode ? (((const int*)act8)[n] != 0) : (act8[n] != 0);
        g_c2[n] = a ? red[0] : __int_as_float(0x7f800000);
    }
}

__global__ void prep_x2_kernel(const float* __restrict__ x) {
    int t = blockIdx.x;
    const float* row = x + (size_t)t * D_;
    float s = 0.f;
    for (int d = threadIdx.x; d < D_; d += 128) { float v = row[d]; s += v * v; }
    __shared__ float red[128];
    red[threadIdx.x] = s;
    __syncthreads();
    for (int off = 64; off; off >>= 1) {
        if (threadIdx.x < off) red[threadIdx.x] += red[threadIdx.x + off];
        __syncthreads();
    }
    if (threadIdx.x == 0) g_x2[t] = red[0];
}

__global__ void init_cand_kernel() {
    int i = blockIdx.x * blockDim.x + threadIdx.x;
    if (i < MTOK * NCAND) g_cand[i] = 0xFFFFFFFFFFFFFFFFULL;
}

// ---------------------------------------------------------------------------
__device__ __forceinline__ unsigned float_to_ordered(float f) {
    unsigned b = __float_as_uint(f);
    return (b & 0x80000000u) ? ~b : (b | 0x80000000u);
}

#define CP16(dst, src) \
    asm volatile("cp.async.cg.shared.global [%0], [%1], 16;\n" ::"r"(dst), "l"(src))
#define CP_COMMIT() asm volatile("cp.async.commit_group;\n" ::)
#define CP_WAIT0()  asm volatile("cp.async.wait_group 0;\n" ::)

// ---------------------------------------------------------------------------
// Selection GEMM: tf32 WMMA (16x16x8) direct from fp32 inputs, 2-stage
// cp.async double buffering, 2 CTAs/SM enforced via launch_bounds.
// No per-element tf32 conversion: HMMA.TF32 truncates fp32 bits; the tiny
// RZ-vs-RN difference only perturbs selection scores, and refine_kernel
// rescores nominees in exact fp32.
// ---------------------------------------------------------------------------
__global__ __launch_bounds__(256, 2) void gemm_tf32_kernel(const float* __restrict__ x,
                                                           const float* __restrict__ codes) {
    __shared__ __align__(16) float sA[2][BM * SROWF];
    __shared__ __align__(16) float sB[2][BN * SROWF];
    __shared__ __align__(16) float sbuf[8][16 * 16];

    const int tid  = threadIdx.x;
    const int lane = tid & 31;
    const int warp = tid >> 5;
    const int wm = warp >> 1;    // 0..3 -> 32 rows each
    const int wn = warp & 1;     // 0..1 -> 64 cols each
    const int mBase  = blockIdx.x * BM;
    const int nChunk = blockIdx.y * NCHUNK;

    const uint32_t sAb = (uint32_t)__cvta_generic_to_shared(&sA[0][0]);
    const uint32_t sBb = (uint32_t)__cvta_generic_to_shared(&sB[0][0]);
    const int STAGEB = BM * SROWF * 4;   // bytes per stage

    const int lr0  = tid >> 2;           // rows 0..63 (and +64)
    const int lseg = (tid & 3) * 8;      // float offset 0,8,16,24 (32B)

    const float* Asrc0 = x + (size_t)(mBase + lr0) * D_ + lseg;
    const float* Asrc1 = x + (size_t)(mBase + lr0 + 64) * D_ + lseg;

    const uint32_t oA0 = (lr0 * SROWF + lseg) * 4;
    const uint32_t oA1 = ((lr0 + 64) * SROWF + lseg) * 4;

    for (int nt = 0; nt < NTILES; nt++) {
        const int nBase = nChunk + nt * BN;
        const float* Bsrc0 = codes + (size_t)(nBase + lr0) * D_ + lseg;
        const float* Bsrc1 = codes + (size_t)(nBase + lr0 + 64) * D_ + lseg;

        wmma::fragment<wmma::accumulator, 16, 16, 8, float> acc[2][4];
#pragma unroll
        for (int mi = 0; mi < 2; mi++)
#pragma unroll
            for (int ni = 0; ni < 4; ni++) wmma::fill_fragment(acc[mi][ni], 0.0f);

        // prefetch k-step 0 into stage 0
        {
            CP16(sAb + oA0,      Asrc0); CP16(sAb + oA0 + 16, Asrc0 + 4);
            CP16(sAb + oA1,      Asrc1); CP16(sAb + oA1 + 16, Asrc1 + 4);
            CP16(sBb + oA0,      Bsrc0); CP16(sBb + oA0 + 16, Bsrc0 + 4);
            CP16(sBb + oA1,      Bsrc1); CP16(sBb + oA1 + 16, Bsrc1 + 4);
            CP_COMMIT();
        }

        for (int kb = 0; kb < NKSTEP; kb++) {
            CP_WAIT0();
            __syncthreads();
            if (kb + 1 < NKSTEP) {
                const int st = (kb + 1) & 1;
                const int kg = (kb + 1) * BK;
                CP16(sAb + st * STAGEB + oA0,      Asrc0 + kg);
                CP16(sAb + st * STAGEB + oA0 + 16, Asrc0 + kg + 4);
                CP16(sAb + st * STAGEB + oA1,      Asrc1 + kg);
                CP16(sAb + st * STAGEB + oA1 + 16, Asrc1 + kg + 4);
                CP16(sBb + st * STAGEB + oA0,      Bsrc0 + kg);
                CP16(sBb + st * STAGEB + oA0 + 16, Bsrc0 + kg + 4);
                CP16(sBb + st * STAGEB + oA1,      Bsrc1 + kg);
                CP16(sBb + st * STAGEB + oA1 + 16, Bsrc1 + kg + 4);
                CP_COMMIT();
            }
            const int st = kb & 1;
#pragma unroll
            for (int ks = 0; ks < 4; ks++) {
                wmma::fragment<wmma::matrix_a, 16, 16, 8, wmma::precision::tf32, wmma::row_major> fa[2];
#pragma unroll
                for (int mi = 0; mi < 2; mi++)
                    wmma::load_matrix_sync(fa[mi], &sA[st][(wm * 32 + mi * 16) * SROWF + ks * 8], SROWF);
#pragma unroll
                for (int ni = 0; ni < 4; ni++) {
                    // smem B is [n][k]; as a KxN matrix that's col_major with ldm=SROWF
                    wmma::fragment<wmma::matrix_b, 16, 16, 8, wmma::precision::tf32, wmma::col_major> fb;
                    wmma::load_matrix_sync(fb, &sB[st][(wn * 64 + ni * 16) * SROWF + ks * 8], SROWF);
                    wmma::mma_sync(acc[0][ni], fa[0], fb, acc[0][ni]);
                    wmma::mma_sync(acc[1][ni], fa[1], fb, acc[1][ni]);
                }
            }
        }

        // epilogue: drain frags (explicit indices), per-TILE min per row, nominate.
        float bestv[2];
        int   besti[2];
#pragma unroll
        for (int q = 0; q < 2; q++) { bestv[q] = __int_as_float(0x7f800000); besti[q] = nBase; }

#pragma unroll
        for (int mi = 0; mi < 2; mi++) {
#pragma unroll
            for (int ni = 0; ni < 4; ni++) {
                wmma::store_matrix_sync(&sbuf[warp][0], acc[mi][ni], 16, wmma::mem_row_major);
                __syncwarp();
                const int lr = lane >> 1;
                const int cb = (lane & 1) * 8;
                const int gcol0 = nBase + wn * 64 + ni * 16 + cb;
#pragma unroll
                for (int c = 0; c < 8; c++) {
                    float dot = sbuf[warp][lr * 16 + cb + c];
                    float s = fmaf(-2.0f, dot, g_c2[gcol0 + c]);
                    if (s < bestv[mi]) { bestv[mi] = s; besti[mi] = gcol0 + c; }
                }
                __syncwarp();
            }
        }

        const int slot = blockIdx.y * NTILES + nt;
#pragma unroll
        for (int mi = 0; mi < 2; mi++) {
            unsigned long long key =
                (((unsigned long long)float_to_ordered(bestv[mi])) << 32) | (unsigned)besti[mi];
            unsigned long long o = __shfl_xor_sync(0xffffffffu, key, 1);
            if (o < key) key = o;
            if ((lane & 1) == 0) {
                int row = mBase + wm * 32 + mi * 16 + (lane >> 1);
                atomicMin(&g_cand[(size_t)row * NCAND + slot], key);
            }
        }
    }
}

// ---------------------------------------------------------------------------
// Exact fp32 rescoring of the 128 nominees per token; emits final outputs.
// ---------------------------------------------------------------------------
__global__ __launch_bounds__(256) void refine_kernel(const float* __restrict__ x,
                                                     const float* __restrict__ codes,
                                                     float* __restrict__ out, int out_size) {
    const int t = blockIdx.x * 8 + (threadIdx.x >> 5);
    const int lane = threadIdx.x & 31;
    if (t >= MTOK) return;

    const float4* xr = (const float4*)(x + (size_t)t * D_);
    float4 xv[6];
#pragma unroll
    for (int j = 0; j < 6; j++) xv[j] = xr[lane + j * 32];

    unsigned long long best = 0xFFFFFFFFFFFFFFFFULL;

    for (int c = 0; c < NCAND; c++) {
        unsigned idx = (unsigned)(g_cand[(size_t)t * NCAND + c] & 0xffffffffu);
        if (idx >= NCODE) continue;             // unwritten/poisoned slot guard
        const float4* cr = (const float4*)(codes + (size_t)idx * D_);
        float s = 0.f;
#pragma unroll
        for (int j = 0; j < 6; j++) {
            float4 cv = cr[lane + j * 32];
            s += xv[j].x * cv.x + xv[j].y * cv.y + xv[j].z * cv.z + xv[j].w * cv.w;
        }
#pragma unroll
        for (int off = 16; off; off >>= 1) s += __shfl_xor_sync(0xffffffffu, s, off);
        float dist = fmaf(-2.0f, s, g_c2[idx]);   // exact fp32 score; inf if inactive
        unsigned long long key =
            (((unsigned long long)float_to_ordered(dist)) << 32) | (unsigned long long)idx;
        if (key < best) best = key;
    }

    if (lane == 0) {
        unsigned u = (unsigned)(best >> 32);
        unsigned b = (u & 0x80000000u) ? (u & 0x7fffffffu) : ~u;
        float s = __uint_as_float(b);
        int idx = (int)(best & 0xffffffffu);
        float dmin = g_x2[t] + s;
        int idx_out = (dmin <= THRv) ? idx : -1;
        if (best == 0xFFFFFFFFFFFFFFFFULL) { idx_out = -1; dmin = __int_as_float(0x7f800000); }
        out[t] = (float)idx_out;
        if (out_size >= 2 * MTOK) out[MTOK + t] = dmin;
    }
}

// ---------------------------------------------------------------------------
extern "C" void kernel_launch(void* const* d_in, const int* in_sizes, int n_in,
                              void* d_out, int out_size) {
    const float* x     = (const float*)d_in[0];
    const float* codes = (const float*)d_in[1];
    const unsigned char* act = (const unsigned char*)d_in[2];

    prep_c2_kernel<<<NCODE, 128>>>(codes, act);
    prep_x2_kernel<<<MTOK, 128>>>(x);
    init_cand_kernel<<<(MTOK * NCAND + 255) / 256, 256>>>();
    gemm_tf32_kernel<<<dim3(MTOK / BM, NSPLIT), 256>>>(x, codes);
    refine_kernel<<<MTOK / 8, 256>>>(x, codes, (float*)d_out, out_size);
}

// round 11
// speedup vs baseline: 2.5800x; 2.1959x over previous
#include <cuda_runtime.h>
#include <cuda_bf16.h>
#include <mma.h>
#include <cstdint>

using namespace nvcuda;

#define MTOK  8192
#define D_    768
#define NCODE 16384
#define THRv  100.0f

#define BM 128
#define BN 128
#define BK 32
#define NSPLIT 16
#define NCHUNK (NCODE / NSPLIT)       // 1024
#define NTILES (NCHUNK / BN)          // 8
#define NKSTEP (D_ / BK)              // 24
#define SROW   40                     // padded bf16 smem row (elems); 80B pitch
#define NCAND  (NSPLIT * NTILES)      // 128 candidates per token

// Scratch (static device memory — allocations are forbidden)
__device__ float g_c2[NCODE];
__device__ float g_x2[MTOK];
__device__ unsigned long long g_cand[MTOK * NCAND];

// ---------------------------------------------------------------------------
// c2[n] = sum codes[n]^2 (exact fp32), +inf if inactive (uint8 or int32 bool).
__global__ void prep_c2_kernel(const float* __restrict__ codes,
                               const unsigned char* __restrict__ act8) {
    int n = blockIdx.x;
    const float* row = codes + (size_t)n * D_;
    float s = 0.f;
    for (int d = threadIdx.x; d < D_; d += 128) { float v = row[d]; s += v * v; }
    __shared__ float red[128];
    red[threadIdx.x] = s;
    __syncthreads();
    for (int off = 64; off; off >>= 1) {
        if (threadIdx.x < off) red[threadIdx.x] += red[threadIdx.x + off];
        __syncthreads();
    }
    if (threadIdx.x == 0) {
        bool int32mode = (act8[0] == 1) && (act8[1] == 0) && (act8[2] == 0) && (act8[3] == 0);
        bool a = int32mode ? (((const int*)act8)[n] != 0) : (act8[n] != 0);
        g_c2[n] = a ? red[0] : __int_as_float(0x7f800000);
    }
}

__global__ void prep_x2_kernel(const float* __restrict__ x) {
    int t = blockIdx.x;
    const float* row = x + (size_t)t * D_;
    float s = 0.f;
    for (int d = threadIdx.x; d < D_; d += 128) { float v = row[d]; s += v * v; }
    __shared__ float red[128];
    red[threadIdx.x] = s;
    __syncthreads();
    for (int off = 64; off; off >>= 1) {
        if (threadIdx.x < off) red[threadIdx.x] += red[threadIdx.x + off];
        __syncthreads();
    }
    if (threadIdx.x == 0) g_x2[t] = red[0];
}

__global__ void init_cand_kernel() {
    int i = blockIdx.x * blockDim.x + threadIdx.x;
    if (i < MTOK * NCAND) g_cand[i] = 0xFFFFFFFFFFFFFFFFULL;
}

// ---------------------------------------------------------------------------
__device__ __forceinline__ unsigned float_to_ordered(float f) {
    unsigned b = __float_as_uint(f);
    return (b & 0x80000000u) ? ~b : (b | 0x80000000u);
}

// Load 8 consecutive fp32, convert to 8 bf16 packed in a uint4 (in registers).
__device__ __forceinline__ uint4 ldcvt8(const float* __restrict__ p) {
    float4 u = *(const float4*)p;
    float4 v = *(const float4*)(p + 4);
    __nv_bfloat162 p0 = __floats2bfloat162_rn(u.x, u.y);
    __nv_bfloat162 p1 = __floats2bfloat162_rn(u.z, u.w);
    __nv_bfloat162 p2 = __floats2bfloat162_rn(v.x, v.y);
    __nv_bfloat162 p3 = __floats2bfloat162_rn(v.z, v.w);
    uint4 r;
    r.x = *(unsigned*)&p0; r.y = *(unsigned*)&p1;
    r.z = *(unsigned*)&p2; r.w = *(unsigned*)&p3;
    return r;
}

// ---------------------------------------------------------------------------
// Selection GEMM: bf16 WMMA (16x16x16), fp32->bf16 converted IN REGISTERS in
// the loader (no global staging buffers — the proven-bad path stays deleted).
// Register double-buffering hides LDG latency; single smem stage.
// Per-token per-TILE winner nominated; exact fp32 refine downstream.
// ---------------------------------------------------------------------------
__global__ __launch_bounds__(256, 2) void gemm_bf16_kernel(const float* __restrict__ x,
                                                           const float* __restrict__ codes) {
    __shared__ __align__(16) __nv_bfloat16 sA[BM * SROW];
    __shared__ __align__(16) __nv_bfloat16 sB[BN * SROW];
    __shared__ __align__(16) float sbuf[8][16 * 16];

    const int tid  = threadIdx.x;
    const int lane = tid & 31;
    const int warp = tid >> 5;
    const int wm = warp >> 1;    // 0..3 -> 32 rows each
    const int wn = warp & 1;     // 0..1 -> 64 cols each
    const int mBase  = blockIdx.x * BM;
    const int nChunk = blockIdx.y * NCHUNK;

    const int lr0  = tid >> 2;           // rows 0..63 (and +64)
    const int lseg = (tid & 3) * 8;      // elem offset 0,8,16,24

    const float* Asrc0 = x + (size_t)(mBase + lr0) * D_ + lseg;
    const float* Asrc1 = x + (size_t)(mBase + lr0 + 64) * D_ + lseg;

    for (int nt = 0; nt < NTILES; nt++) {
        const int nBase = nChunk + nt * BN;
        const float* Bsrc0 = codes + (size_t)(nBase + lr0) * D_ + lseg;
        const float* Bsrc1 = codes + (size_t)(nBase + lr0 + 64) * D_ + lseg;

        wmma::fragment<wmma::accumulator, 16, 16, 16, float> acc[2][4];
#pragma unroll
        for (int mi = 0; mi < 2; mi++)
#pragma unroll
            for (int ni = 0; ni < 4; ni++) wmma::fill_fragment(acc[mi][ni], 0.0f);

        // prologue: load+convert k-step 0 into registers
        uint4 ra0 = ldcvt8(Asrc0), ra1 = ldcvt8(Asrc1);
        uint4 rb0 = ldcvt8(Bsrc0), rb1 = ldcvt8(Bsrc1);

        for (int kb = 0; kb < NKSTEP; kb++) {
            __syncthreads();   // previous k-step's MMAs done reading smem
            *(uint4*)&sA[lr0 * SROW + lseg]        = ra0;
            *(uint4*)&sA[(lr0 + 64) * SROW + lseg] = ra1;
            *(uint4*)&sB[lr0 * SROW + lseg]        = rb0;
            *(uint4*)&sB[(lr0 + 64) * SROW + lseg] = rb1;
            __syncthreads();
            if (kb + 1 < NKSTEP) {
                const int kg = (kb + 1) * BK;
                ra0 = ldcvt8(Asrc0 + kg); ra1 = ldcvt8(Asrc1 + kg);
                rb0 = ldcvt8(Bsrc0 + kg); rb1 = ldcvt8(Bsrc1 + kg);
            }
#pragma unroll
            for (int ks = 0; ks < 2; ks++) {
                wmma::fragment<wmma::matrix_a, 16, 16, 16, __nv_bfloat16, wmma::row_major> fa[2];
#pragma unroll
                for (int mi = 0; mi < 2; mi++)
                    wmma::load_matrix_sync(fa[mi], &sA[(wm * 32 + mi * 16) * SROW + ks * 16], SROW);
#pragma unroll
                for (int ni = 0; ni < 4; ni++) {
                    // smem B is [n][k]; as a KxN matrix that's col_major with ldm=SROW
                    wmma::fragment<wmma::matrix_b, 16, 16, 16, __nv_bfloat16, wmma::col_major> fb;
                    wmma::load_matrix_sync(fb, &sB[(wn * 64 + ni * 16) * SROW + ks * 16], SROW);
                    wmma::mma_sync(acc[0][ni], fa[0], fb, acc[0][ni]);
                    wmma::mma_sync(acc[1][ni], fa[1], fb, acc[1][ni]);
                }
            }
        }

        // epilogue: drain frags (explicit indices), per-TILE min per row, nominate.
        float bestv[2];
        int   besti[2];
#pragma unroll
        for (int q = 0; q < 2; q++) { bestv[q] = __int_as_float(0x7f800000); besti[q] = nBase; }

#pragma unroll
        for (int mi = 0; mi < 2; mi++) {
#pragma unroll
            for (int ni = 0; ni < 4; ni++) {
                wmma::store_matrix_sync(&sbuf[warp][0], acc[mi][ni], 16, wmma::mem_row_major);
                __syncwarp();
                const int lr = lane >> 1;
                const int cb = (lane & 1) * 8;
                const int gcol0 = nBase + wn * 64 + ni * 16 + cb;
#pragma unroll
                for (int c = 0; c < 8; c++) {
                    float dot = sbuf[warp][lr * 16 + cb + c];
                    float s = fmaf(-2.0f, dot, g_c2[gcol0 + c]);
                    if (s < bestv[mi]) { bestv[mi] = s; besti[mi] = gcol0 + c; }
                }
                __syncwarp();
            }
        }

        const int slot = blockIdx.y * NTILES + nt;
#pragma unroll
        for (int mi = 0; mi < 2; mi++) {
            unsigned long long key =
                (((unsigned long long)float_to_ordered(bestv[mi])) << 32) | (unsigned)besti[mi];
            unsigned long long o = __shfl_xor_sync(0xffffffffu, key, 1);
            if (o < key) key = o;
            if ((lane & 1) == 0) {
                int row = mBase + wm * 32 + mi * 16 + (lane >> 1);
                atomicMin(&g_cand[(size_t)row * NCAND + slot], key);
            }
        }
    }
}

// ---------------------------------------------------------------------------
// Exact fp32 rescoring of the 128 nominees per token; emits final outputs.
// ---------------------------------------------------------------------------
__global__ __launch_bounds__(256) void refine_kernel(const float* __restrict__ x,
                                                     const float* __restrict__ codes,
                                                     float* __restrict__ out, int out_size) {
    const int t = blockIdx.x * 8 + (threadIdx.x >> 5);
    const int lane = threadIdx.x & 31;
    if (t >= MTOK) return;

    const float4* xr = (const float4*)(x + (size_t)t * D_);
    float4 xv[6];
#pragma unroll
    for (int j = 0; j < 6; j++) xv[j] = xr[lane + j * 32];

    unsigned long long best = 0xFFFFFFFFFFFFFFFFULL;

    for (int c = 0; c < NCAND; c++) {
        unsigned idx = (unsigned)(g_cand[(size_t)t * NCAND + c] & 0xffffffffu);
        if (idx >= NCODE) continue;             // unwritten/poisoned slot guard
        const float4* cr = (const float4*)(codes + (size_t)idx * D_);
        float s = 0.f;
#pragma unroll
        for (int j = 0; j < 6; j++) {
            float4 cv = cr[lane + j * 32];
            s += xv[j].x * cv.x + xv[j].y * cv.y + xv[j].z * cv.z + xv[j].w * cv.w;
        }
#pragma unroll
        for (int off = 16; off; off >>= 1) s += __shfl_xor_sync(0xffffffffu, s, off);
        float dist = fmaf(-2.0f, s, g_c2[idx]);   // exact fp32 score; inf if inactive
        unsigned long long key =
            (((unsigned long long)float_to_ordered(dist)) << 32) | (unsigned long long)idx;
        if (key < best) best = key;
    }

    if (lane == 0) {
        unsigned u = (unsigned)(best >> 32);
        unsigned b = (u & 0x80000000u) ? (u & 0x7fffffffu) : ~u;
        float s = __uint_as_float(b);
        int idx = (int)(best & 0xffffffffu);
        float dmin = g_x2[t] + s;
        int idx_out = (dmin <= THRv) ? idx : -1;
        if (best == 0xFFFFFFFFFFFFFFFFULL) { idx_out = -1; dmin = __int_as_float(0x7f800000); }
        out[t] = (float)idx_out;
        if (out_size >= 2 * MTOK) out[MTOK + t] = dmin;
    }
}

// ---------------------------------------------------------------------------
extern "C" void kernel_launch(void* const* d_in, const int* in_sizes, int n_in,
                              void* d_out, int out_size) {
    const float* x     = (const float*)d_in[0];
    const float* codes = (const float*)d_in[1];
    const unsigned char* act = (const unsigned char*)d_in[2];

    prep_c2_kernel<<<NCODE, 128>>>(codes, act);
    prep_x2_kernel<<<MTOK, 128>>>(x);
    init_cand_kernel<<<(MTOK * NCAND + 255) / 256, 256>>>();
    gemm_bf16_kernel<<<dim3(MTOK / BM, NSPLIT), 256>>>(x, codes);
    refine_kernel<<<MTOK / 8, 256>>>(x, codes, (float*)d_out, out_size);
}

// round 13
// speedup vs baseline: 3.8790x; 1.5035x over previous
#include <cuda_runtime.h>
#include <cuda_bf16.h>
#include <mma.h>
#include <cstdint>

using namespace nvcuda;

#define MTOK  8192
#define D_    768
#define NCODE 16384
#define THRv  100.0f

#define BM 128
#define BN 128
#define BK 32
#define NSPLIT 16
#define NCHUNK (NCODE / NSPLIT)       // 1024
#define NTILES (NCHUNK / BN)          // 8
#define NKSTEP (D_ / BK)              // 24
#define SROW   40                     // padded bf16 smem row (elems); 80B pitch
#define NCAND  (NSPLIT * 2)           // 32 slots: one per (split, column-half)

// Scratch (static device memory — allocations are forbidden).
// Referenced ONLY from device code by symbol (host-passing a __device__
// symbol as a kernel arg is UB and was the R2-R6 bug).
__device__ float g_c2[NCODE];
__device__ float g_x2[MTOK];
__device__ unsigned long long g_cand[MTOK * NCAND];
__device__ __align__(16) __nv_bfloat16 g_xb[MTOK * D_];
__device__ __align__(16) __nv_bfloat16 g_cb[NCODE * D_];

// ---------------------------------------------------------------------------
// fp32 -> bf16 staging, writing the __device__ arrays BY SYMBOL.
__global__ void cvt_x_kernel(const float* __restrict__ in) {
    int i = blockIdx.x * blockDim.x + threadIdx.x;   // one uint4 (8 bf16) per thread
    if (i >= MTOK * D_ / 8) return;
    float4 u = ((const float4*)in)[2 * i];
    float4 v = ((const float4*)in)[2 * i + 1];
    __nv_bfloat162 p0 = __floats2bfloat162_rn(u.x, u.y);
    __nv_bfloat162 p1 = __floats2bfloat162_rn(u.z, u.w);
    __nv_bfloat162 p2 = __floats2bfloat162_rn(v.x, v.y);
    __nv_bfloat162 p3 = __floats2bfloat162_rn(v.z, v.w);
    uint4 r;
    r.x = *(unsigned*)&p0; r.y = *(unsigned*)&p1;
    r.z = *(unsigned*)&p2; r.w = *(unsigned*)&p3;
    ((uint4*)g_xb)[i] = r;
}

__global__ void cvt_c_kernel(const float* __restrict__ in) {
    int i = blockIdx.x * blockDim.x + threadIdx.x;
    if (i >= NCODE * D_ / 8) return;
    float4 u = ((const float4*)in)[2 * i];
    float4 v = ((const float4*)in)[2 * i + 1];
    __nv_bfloat162 p0 = __floats2bfloat162_rn(u.x, u.y);
    __nv_bfloat162 p1 = __floats2bfloat162_rn(u.z, u.w);
    __nv_bfloat162 p2 = __floats2bfloat162_rn(v.x, v.y);
    __nv_bfloat162 p3 = __floats2bfloat162_rn(v.z, v.w);
    uint4 r;
    r.x = *(unsigned*)&p0; r.y = *(unsigned*)&p1;
    r.z = *(unsigned*)&p2; r.w = *(unsigned*)&p3;
    ((uint4*)g_cb)[i] = r;
}

// ---------------------------------------------------------------------------
// c2[n] = sum codes[n]^2 (exact fp32), +inf if inactive (uint8 or int32 bool).
__global__ void prep_c2_kernel(const float* __restrict__ codes,
                               const unsigned char* __restrict__ act8) {
    int n = blockIdx.x;
    const float* row = codes + (size_t)n * D_;
    float s = 0.f;
    for (int d = threadIdx.x; d < D_; d += 128) { float v = row[d]; s += v * v; }
    __shared__ float red[128];
    red[threadIdx.x] = s;
    __syncthreads();
    for (int off = 64; off; off >>= 1) {
        if (threadIdx.x < off) red[threadIdx.x] += red[threadIdx.x + off];
        __syncthreads();
    }
    if (threadIdx.x == 0) {
        bool int32mode = (act8[0] == 1) && (act8[1] == 0) && (act8[2] == 0) && (act8[3] == 0);
        bool a = int32mode ? (((const int*)act8)[n] != 0) : (act8[n] != 0);
        g_c2[n] = a ? red[0] : __int_as_float(0x7f800000);
    }
}

__global__ void prep_x2_kernel(const float* __restrict__ x) {
    int t = blockIdx.x;
    const float* row = x + (size_t)t * D_;
    float s = 0.f;
    for (int d = threadIdx.x; d < D_; d += 128) { float v = row[d]; s += v * v; }
    __shared__ float red[128];
    red[threadIdx.x] = s;
    __syncthreads();
    for (int off = 64; off; off >>= 1) {
        if (threadIdx.x < off) red[threadIdx.x] += red[threadIdx.x + off];
        __syncthreads();
    }
    if (threadIdx.x == 0) g_x2[t] = red[0];
}

// ---------------------------------------------------------------------------
__device__ __forceinline__ unsigned float_to_ordered(float f) {
    unsigned b = __float_as_uint(f);
    return (b & 0x80000000u) ? ~b : (b | 0x80000000u);
}

// ---------------------------------------------------------------------------
// Selection GEMM: bf16 WMMA, 4 warps of 64x64 (2x2), staged-bf16 LDG,
// register double-buffered single-stage smem. Per-(split, col-half) winner
// per token kept in registers; DISJOINT plain stores (wn in slot index —
// the R12 race is gone).
// ---------------------------------------------------------------------------
__global__ __launch_bounds__(128, 2) void gemm_bf16_kernel() {
    __shared__ __align__(16) __nv_bfloat16 sA[BM * SROW];
    __shared__ __align__(16) __nv_bfloat16 sB[BN * SROW];
    __shared__ __align__(16) float sbuf[4][16 * 16];

    const int tid  = threadIdx.x;
    const int lane = tid & 31;
    const int warp = tid >> 5;      // 0..3
    const int wm = warp & 1;        // 0..1 -> 64 rows each
    const int wn = warp >> 1;       // 0..1 -> 64 cols each
    const int mBase  = blockIdx.x * BM;
    const int nChunk = blockIdx.y * NCHUNK;

    const int lrow = tid >> 2;           // 0..31 (rows +0,+32,+64,+96)
    const int lseg = (tid & 3) * 8;      // elem offset 0,8,16,24

    const __nv_bfloat16* Abase = g_xb + (size_t)(mBase + lrow) * D_ + lseg;

    // running per-row winners for this (split, col-half)
    float bestv[4];
    int   besti[4];
#pragma unroll
    for (int q = 0; q < 4; q++) { bestv[q] = __int_as_float(0x7f800000); besti[q] = nChunk; }

    for (int nt = 0; nt < NTILES; nt++) {
        const int nBase = nChunk + nt * BN;
        const __nv_bfloat16* Bbase = g_cb + (size_t)(nBase + lrow) * D_ + lseg;

        wmma::fragment<wmma::accumulator, 16, 16, 16, float> acc[4][4];
#pragma unroll
        for (int mi = 0; mi < 4; mi++)
#pragma unroll
            for (int ni = 0; ni < 4; ni++) wmma::fill_fragment(acc[mi][ni], 0.0f);

        // prologue: k-step 0 into registers
        uint4 rA[4], rB[4];
#pragma unroll
        for (int r = 0; r < 4; r++) {
            rA[r] = *(const uint4*)(Abase + (size_t)(r * 32) * D_);
            rB[r] = *(const uint4*)(Bbase + (size_t)(r * 32) * D_);
        }

        for (int kb = 0; kb < NKSTEP; kb++) {
            __syncthreads();   // previous k-step's MMAs done reading smem
#pragma unroll
            for (int r = 0; r < 4; r++) {
                *(uint4*)&sA[(lrow + r * 32) * SROW + lseg] = rA[r];
                *(uint4*)&sB[(lrow + r * 32) * SROW + lseg] = rB[r];
            }
            __syncthreads();
            if (kb + 1 < NKSTEP) {
                const int kg = (kb + 1) * BK;
#pragma unroll
                for (int r = 0; r < 4; r++) {
                    rA[r] = *(const uint4*)(Abase + (size_t)(r * 32) * D_ + kg);
                    rB[r] = *(const uint4*)(Bbase + (size_t)(r * 32) * D_ + kg);
                }
            }
#pragma unroll
            for (int ks = 0; ks < 2; ks++) {
                wmma::fragment<wmma::matrix_a, 16, 16, 16, __nv_bfloat16, wmma::row_major> fa[4];
#pragma unroll
                for (int mi = 0; mi < 4; mi++)
                    wmma::load_matrix_sync(fa[mi], &sA[(wm * 64 + mi * 16) * SROW + ks * 16], SROW);
#pragma unroll
                for (int ni = 0; ni < 4; ni++) {
                    // smem B is [n][k]; as a KxN matrix that's col_major with ldm=SROW
                    wmma::fragment<wmma::matrix_b, 16, 16, 16, __nv_bfloat16, wmma::col_major> fb;
                    wmma::load_matrix_sync(fb, &sB[(wn * 64 + ni * 16) * SROW + ks * 16], SROW);
#pragma unroll
                    for (int mi = 0; mi < 4; mi++)
                        wmma::mma_sync(acc[mi][ni], fa[mi], fb, acc[mi][ni]);
                }
            }
        }

        // drain frags through smem (explicit indices), update running mins
#pragma unroll
        for (int mi = 0; mi < 4; mi++) {
#pragma unroll
            for (int ni = 0; ni < 4; ni++) {
                wmma::store_matrix_sync(&sbuf[warp][0], acc[mi][ni], 16, wmma::mem_row_major);
                __syncwarp();
                const int lr = lane >> 1;
                const int cb = (lane & 1) * 8;
                const int gcol0 = nBase + wn * 64 + ni * 16 + cb;
#pragma unroll
                for (int c = 0; c < 8; c++) {
                    float dot = sbuf[warp][lr * 16 + cb + c];
                    float s = fmaf(-2.0f, dot, g_c2[gcol0 + c]);
                    if (s < bestv[mi]) { bestv[mi] = s; besti[mi] = gcol0 + c; }
                }
                __syncwarp();
            }
        }
    }

    // merge lane pairs (same row, col quadrants within the half) and store
    // this (split, half)'s winner per row into its OWN slot — no races.
    const int slot = blockIdx.y * 2 + wn;
#pragma unroll
    for (int mi = 0; mi < 4; mi++) {
        unsigned long long key =
            (((unsigned long long)float_to_ordered(bestv[mi])) << 32) | (unsigned)besti[mi];
        unsigned long long o = __shfl_xor_sync(0xffffffffu, key, 1);
        if (o < key) key = o;
        if ((lane & 1) == 0) {
            int row = mBase + wm * 64 + mi * 16 + (lane >> 1);
            g_cand[(size_t)row * NCAND + slot] = key;
        }
    }
}

// ---------------------------------------------------------------------------
// Exact fp32 rescoring of the 32 nominees per token; emits final outputs.
// ---------------------------------------------------------------------------
__global__ __launch_bounds__(256) void refine_kernel(const float* __restrict__ x,
                                                     const float* __restrict__ codes,
                                                     float* __restrict__ out, int out_size) {
    const int t = blockIdx.x * 8 + (threadIdx.x >> 5);
    const int lane = threadIdx.x & 31;
    if (t >= MTOK) return;

    const float4* xr = (const float4*)(x + (size_t)t * D_);
    float4 xv[6];
#pragma unroll
    for (int j = 0; j < 6; j++) xv[j] = xr[lane + j * 32];

    unsigned long long best = 0xFFFFFFFFFFFFFFFFULL;

    for (int c = 0; c < NCAND; c++) {
        unsigned idx = (unsigned)(g_cand[(size_t)t * NCAND + c] & 0xffffffffu);
        if (idx >= NCODE) continue;             // safety guard
        const float4* cr = (const float4*)(codes + (size_t)idx * D_);
        float s = 0.f;
#pragma unroll
        for (int j = 0; j < 6; j++) {
            float4 cv = cr[lane + j * 32];
            s += xv[j].x * cv.x + xv[j].y * cv.y + xv[j].z * cv.z + xv[j].w * cv.w;
        }
#pragma unroll
        for (int off = 16; off; off >>= 1) s += __shfl_xor_sync(0xffffffffu, s, off);
        float dist = fmaf(-2.0f, s, g_c2[idx]);   // exact fp32 score; inf if inactive
        unsigned long long key =
            (((unsigned long long)float_to_ordered(dist)) << 32) | (unsigned long long)idx;
        if (key < best) best = key;
    }

    if (lane == 0) {
        unsigned u = (unsigned)(best >> 32);
        unsigned b = (u & 0x80000000u) ? (u & 0x7fffffffu) : ~u;
        float s = __uint_as_float(b);
        int idx = (int)(best & 0xffffffffu);
        float dmin = g_x2[t] + s;
        int idx_out = (dmin <= THRv) ? idx : -1;
        if (best == 0xFFFFFFFFFFFFFFFFULL) { idx_out = -1; dmin = __int_as_float(0x7f800000); }
        out[t] = (float)idx_out;
        if (out_size >= 2 * MTOK) out[MTOK + t] = dmin;
    }
}

// ---------------------------------------------------------------------------
extern "C" void kernel_launch(void* const* d_in, const int* in_sizes, int n_in,
                              void* d_out, int out_size) {
    const float* x     = (const float*)d_in[0];
    const float* codes = (const float*)d_in[1];
    const unsigned char* act = (const unsigned char*)d_in[2];

    cvt_x_kernel<<<(MTOK * D_ / 8 + 255) / 256, 256>>>(x);
    cvt_c_kernel<<<(NCODE * D_ / 8 + 255) / 256, 256>>>(codes);
    prep_c2_kernel<<<NCODE, 128>>>(codes, act);
    prep_x2_kernel<<<MTOK, 128>>>(x);
    gemm_bf16_kernel<<<dim3(MTOK / BM, NSPLIT), 128>>>();
    refine_kernel<<<MTOK / 8, 256>>>(x, codes, (float*)d_out, out_size);
}